// round 9
// baseline (speedup 1.0000x reference)
#include <cuda_runtime.h>

#define NMAX 50000
#define EMAX 800000
#define HDIM 128
#define GNUM 256
#define ODIM 10
#define BN_EPS 1e-5f

// ---------------- scratch: device globals, accessed DIRECTLY by kernels ----------------
__device__ __align__(16) float g_h  [NMAX * HDIM];   // node features (GEMM out / BN out)
__device__ __align__(16) float g_agg[NMAX * HDIM];   // aggregation target
__device__ int   g_degi[NMAX];                        // in-degree (edges only)
__device__ int   g_row [NMAX + 1];                    // CSR row offsets (by dst)
__device__ int   g_cur [NMAX];                        // fill cursors
__device__ int   g_col [EMAX];                        // CSR column (src) per edge
__device__ float g_dis [NMAX];                        // rsqrt(deg + 1)
__device__ float g_stats[512];                        // sum | sumsq | scale | shift (128 each)
__device__ __align__(16) float g_pool[GNUM * HDIM];
__device__ float g_cnt [GNUM];

// ---------------- CSR build ----------------
__global__ void k_deg_zero(int n) {
    int i = blockIdx.x * blockDim.x + threadIdx.x;
    if (i < n) g_degi[i] = 0;
}

__global__ void k_deg_count(const int* __restrict__ dst, int E) {
    int e = blockIdx.x * blockDim.x + threadIdx.x;
    if (e < E) atomicAdd(&g_degi[dst[e]], 1);
}

// single block, 1024 threads: exclusive scan of g_degi into g_row[0..n]
__global__ void k_scan(int n) {
    __shared__ int sdata[1024];
    const int t = threadIdx.x;
    const int chunk = (n + 1023) >> 10;
    int beg = t * chunk;
    int end = min(n, beg + chunk);
    if (beg > end) beg = end;
    int s = 0;
    for (int i = beg; i < end; i++) s += g_degi[i];
    sdata[t] = s;
    __syncthreads();
    for (int off = 1; off < 1024; off <<= 1) {
        int v = (t >= off) ? sdata[t - off] : 0;
        __syncthreads();
        sdata[t] += v;
        __syncthreads();
    }
    int run = t ? sdata[t - 1] : 0;
    for (int i = beg; i < end; i++) { g_row[i] = run; run += g_degi[i]; }
    if (end == n) g_row[n] = run;
}

__global__ void k_prep(int n) {
    int i = blockIdx.x * blockDim.x + threadIdx.x;
    if (i < n) {
        g_dis[i] = rsqrtf((float)(g_degi[i] + 1));
        g_cur[i] = g_row[i];
    }
}

__global__ void k_fill(const int* __restrict__ src, const int* __restrict__ dst, int E) {
    int e = blockIdx.x * blockDim.x + threadIdx.x;
    if (e < E) {
        int d = dst[e];
        int p = atomicAdd(&g_cur[d], 1);
        g_col[p] = src[e];
    }
}

// ---------------- GEMM: g_h = A @ W, A = (Aext ? Aext : g_h), [n,128]x[128,128] ----------------
// Static shared memory only. K chunked in 4 steps of 32.
// In-place safe: each block reads only its own 64 rows, writes them after all reads.
__global__ void k_gemm(const float* __restrict__ Aext, const float* __restrict__ W, int n) {
    const float* A = Aext ? Aext : (const float*)g_h;
    __shared__ float sW[32][128];   // 16 KB
    __shared__ float sA[64][33];    // 8.4 KB (pad 33)
    const int t = threadIdx.x;       // 256 threads
    const int row0 = blockIdx.x * 64;
    const int tx = t & 15;           // cols tx*8..tx*8+7
    const int ty = t >> 4;           // rows ty*4..ty*4+3

    float acc[4][8];
    #pragma unroll
    for (int r = 0; r < 4; r++)
        #pragma unroll
        for (int c = 0; c < 8; c++) acc[r][c] = 0.f;

    for (int kc = 0; kc < 4; kc++) {
        const int k0 = kc * 32;
        const float4* W4 = (const float4*)(W + k0 * 128);
        float4* sW4 = (float4*)&sW[0][0];
        #pragma unroll
        for (int i = t; i < 1024; i += 256) sW4[i] = W4[i];
        #pragma unroll
        for (int i = t; i < 512; i += 256) {
            int r = i >> 3, c4 = i & 7;
            int gr = row0 + r;
            float4 v = make_float4(0.f, 0.f, 0.f, 0.f);
            if (gr < n) v = *(const float4*)(A + gr * 128 + k0 + c4 * 4);
            sA[r][c4 * 4 + 0] = v.x; sA[r][c4 * 4 + 1] = v.y;
            sA[r][c4 * 4 + 2] = v.z; sA[r][c4 * 4 + 3] = v.w;
        }
        __syncthreads();

        #pragma unroll
        for (int k = 0; k < 32; k++) {
            float4 w0 = *(const float4*)&sW[k][tx * 8];
            float4 w1 = *(const float4*)&sW[k][tx * 8 + 4];
            float ar[4];
            #pragma unroll
            for (int r = 0; r < 4; r++) ar[r] = sA[ty * 4 + r][k];
            float wc[8] = {w0.x, w0.y, w0.z, w0.w, w1.x, w1.y, w1.z, w1.w};
            #pragma unroll
            for (int r = 0; r < 4; r++)
                #pragma unroll
                for (int c = 0; c < 8; c++) acc[r][c] += ar[r] * wc[c];
        }
        __syncthreads();
    }

    #pragma unroll
    for (int r = 0; r < 4; r++) {
        int gr = row0 + ty * 4 + r;
        if (gr < n) {
            *(float4*)&g_h[gr * 128 + tx * 8]     = make_float4(acc[r][0], acc[r][1], acc[r][2], acc[r][3]);
            *(float4*)&g_h[gr * 128 + tx * 8 + 4] = make_float4(acc[r][4], acc[r][5], acc[r][6], acc[r][7]);
        }
    }
}

// ---------------- aggregation: warp per dst node, atomic-free gather ----------------
// g_agg[d] = g_h[d]*dis[d]^2 + sum_{e: dst=d} g_h[src_e]*dis[src_e]*dis[d]
__global__ void k_agg_gather(int n) {
    int node = (blockIdx.x * blockDim.x + threadIdx.x) >> 5;
    if (node >= n) return;
    const int lane = threadIdx.x & 31;
    const float dd = g_dis[node];

    float4 acc = *(const float4*)&g_h[node * 128 + (lane << 2)];
    float dd2 = dd * dd;
    acc.x *= dd2; acc.y *= dd2; acc.z *= dd2; acc.w *= dd2;

    const int beg = g_row[node];
    const int end = g_row[node + 1];
    for (int base = beg; base < end; base += 32) {
        int idx = base + lane;
        int s = 0; float ns = 0.f;
        if (idx < end) {
            s = g_col[idx];
            ns = g_dis[s] * dd;
        }
        int cnt = min(32, end - base);
        for (int k = 0; k < cnt; k++) {
            int   sk = __shfl_sync(0xffffffffu, s, k);
            float nk = __shfl_sync(0xffffffffu, ns, k);
            float4 v = *(const float4*)&g_h[sk * 128 + (lane << 2)];
            acc.x += v.x * nk; acc.y += v.y * nk;
            acc.z += v.z * nk; acc.w += v.w * nk;
        }
    }
    *(float4*)&g_agg[node * 128 + (lane << 2)] = acc;
}

// ---------------- BatchNorm ----------------
__global__ void k_stats_zero() {
    g_stats[threadIdx.x] = 0.f;   // 256 threads cover sum+sumsq
}

__global__ void k_stats(int n) {
    int c = threadIdx.x;   // 128
    float s = 0.f, s2 = 0.f;
    for (int r = blockIdx.x; r < n; r += gridDim.x) {
        float v = g_agg[r * 128 + c];
        s += v; s2 += v * v;
    }
    atomicAdd(&g_stats[c], s);
    atomicAdd(&g_stats[128 + c], s2);
}

__global__ void k_finalize_stats(const float* __restrict__ gma, const float* __restrict__ bet, int n) {
    int c = threadIdx.x;   // 128
    float inv_n = 1.0f / (float)n;
    float mu  = g_stats[c] * inv_n;
    float var = g_stats[128 + c] * inv_n - mu * mu;
    float scale = gma[c] * rsqrtf(var + BN_EPS);
    g_stats[256 + c] = scale;
    g_stats[384 + c] = bet[c] - mu * scale;
}

__global__ void k_bn_relu(int total) {
    int i = blockIdx.x * blockDim.x + threadIdx.x;
    if (i < total) {
        int c = i & 127;
        float v = fmaf(g_agg[i], g_stats[256 + c], g_stats[384 + c]);
        g_h[i] = fmaxf(v, 0.f);
    }
}

// ---------------- pooling (batch sorted: run-length accumulate, flush at boundaries) ----------------
__global__ void k_pool_zero() {
    int i = blockIdx.x * blockDim.x + threadIdx.x;
    if (i < GNUM * HDIM) g_pool[i] = 0.f;
    if (i < GNUM) g_cnt[i] = 0.f;
}

__global__ void k_pool(const int* __restrict__ batch, int n) {
    const int c = threadIdx.x;   // 128 cols
    const int chunk = (n + gridDim.x - 1) / gridDim.x;
    const int i0 = blockIdx.x * chunk;
    const int i1 = min(n, i0 + chunk);
    if (i0 >= i1) return;

    int curg = batch[i0];
    float acc = 0.f, cacc = 0.f;
    for (int i = i0; i < i1; i++) {
        int g = batch[i];
        if (g != curg) {
            atomicAdd(&g_pool[curg * 128 + c], acc);
            if (c == 0) atomicAdd(&g_cnt[curg], cacc);
            acc = 0.f; cacc = 0.f; curg = g;
        }
        acc += g_h[i * 128 + c];
        cacc += 1.f;
    }
    atomicAdd(&g_pool[curg * 128 + c], acc);
    if (c == 0) atomicAdd(&g_cnt[curg], cacc);
}

// block per graph: out[g] = (pool[g]/max(cnt,1)) @ Wout + bout
__global__ void k_out(const float* __restrict__ Wout, const float* __restrict__ bout,
                      float* __restrict__ out) {
    __shared__ float p[128];
    int g = blockIdx.x;
    float c = fmaxf(g_cnt[g], 1.0f);
    p[threadIdx.x] = g_pool[g * 128 + threadIdx.x] / c;
    __syncthreads();
    if (threadIdx.x < ODIM) {
        float s = bout[threadIdx.x];
        #pragma unroll 16
        for (int f = 0; f < 128; f++) s += p[f] * Wout[f * ODIM + threadIdx.x];
        out[g * ODIM + threadIdx.x] = s;
    }
}

// ---------------- launch ----------------
extern "C" void kernel_launch(void* const* d_in, const int* in_sizes, int n_in,
                              void* d_out, int out_size) {
    const float* x     = (const float*)d_in[0];
    const int*   ei    = (const int*)d_in[1];     // int32! (JAX default int, x64 disabled)
    const int*   batch = (const int*)d_in[2];     // int32!
    const float* W1    = (const float*)d_in[3];
    // d_in[4] = b1: cancels in training-mode BatchNorm
    const float* g1    = (const float*)d_in[5];
    const float* be1   = (const float*)d_in[6];
    const float* W2    = (const float*)d_in[7];
    // d_in[8] = b2: cancels
    const float* g2    = (const float*)d_in[9];
    const float* be2   = (const float*)d_in[10];
    const float* Wout  = (const float*)d_in[11];
    const float* bout  = (const float*)d_in[12];
    float*       out   = (float*)d_out;

    const int n = in_sizes[0] / HDIM;
    const int E = in_sizes[1] / 2;
    const int* src = ei;         // edge_index[0]
    const int* dst = ei + E;     // edge_index[1]

    const int TB = 256;
    const int nodeBlocks     = (n + TB - 1) / TB;
    const int elemBlocks     = (n * HDIM + TB - 1) / TB;
    const int edgeBlocks     = (E + TB - 1) / TB;
    const int nodeWarpBlocks = (n + (TB / 32) - 1) / (TB / 32);
    const int gemmBlocks     = (n + 63) / 64;

    // --- CSR build + normalization ---
    k_deg_zero<<<nodeBlocks, TB>>>(n);
    k_deg_count<<<edgeBlocks, TB>>>(dst, E);
    k_scan<<<1, 1024>>>(n);
    k_prep<<<nodeBlocks, TB>>>(n);
    k_fill<<<edgeBlocks, TB>>>(src, dst, E);

    // --- layer 1 ---
    k_gemm<<<gemmBlocks, TB>>>(x, W1, n);
    k_agg_gather<<<nodeWarpBlocks, TB>>>(n);
    k_stats_zero<<<1, 256>>>();
    k_stats<<<256, 128>>>(n);
    k_finalize_stats<<<1, 128>>>(g1, be1, n);
    k_bn_relu<<<elemBlocks, TB>>>(n * HDIM);

    // --- layer 2 (GEMM reads g_h in-place) ---
    k_gemm<<<gemmBlocks, TB>>>(nullptr, W2, n);
    k_agg_gather<<<nodeWarpBlocks, TB>>>(n);
    k_stats_zero<<<1, 256>>>();
    k_stats<<<256, 128>>>(n);
    k_finalize_stats<<<1, 128>>>(g2, be2, n);
    k_bn_relu<<<elemBlocks, TB>>>(n * HDIM);

    // --- pooling + output ---
    k_pool_zero<<<(GNUM * HDIM + TB - 1) / TB, TB>>>();
    k_pool<<<256, 128>>>(batch, n);
    k_out<<<GNUM, 128>>>(Wout, bout, out);
}